// round 10
// baseline (speedup 1.0000x reference)
#include <cuda_runtime.h>
#include <cstdint>

#define NUM_SEG 100000
#define DIM 32
#define TPB 256
#define ROWS_PER_BLK 256
#define TILE_BYTES (ROWS_PER_BLK * DIM * 4)   // 32 KB

// Scratch (allocation-free rule => __device__ global)
__device__ int g_icounts[NUM_SEG];

__device__ __forceinline__ uint32_t smem_u32(const void* p) {
    uint32_t a;
    asm("{ .reg .u64 t; cvta.to.shared.u64 t, %1; cvt.u32.u64 %0, t; }" : "=r"(a) : "l"(p));
    return a;
}

// ---- Pass 1: segment counts (int REDs, no return value) ----
__global__ void __launch_bounds__(TPB) count_kernel(
    const int4* __restrict__ idx4, int n4,
    const int* __restrict__ idx, int nrows)
{
    int i = blockIdx.x * blockDim.x + threadIdx.x;
    if (i < n4) {
        int4 v = idx4[i];
        if ((unsigned)v.x < NUM_SEG) atomicAdd(&g_icounts[v.x], 1);
        if ((unsigned)v.y < NUM_SEG) atomicAdd(&g_icounts[v.y], 1);
        if ((unsigned)v.z < NUM_SEG) atomicAdd(&g_icounts[v.z], 1);
        if ((unsigned)v.w < NUM_SEG) atomicAdd(&g_icounts[v.w], 1);
    }
    if (i == 0) {
        for (int r = n4 * 4; r < nrows; r++) {
            int s = idx[r];
            if ((unsigned)s < NUM_SEG) atomicAdd(&g_icounts[s], 1);
        }
    }
}

// ---- Pass 2: TMA bulk-in, scale tile by 1/count in smem, bulk-reduce. ----
// No count atomics here (they were 20% of the LTS atomic sector workload) and
// no divide pass afterwards: the reduce writes pre-scaled values.
__global__ void __launch_bounds__(TPB) scatter_kernel(
    const float* __restrict__ x,
    const int* __restrict__ index,
    float* __restrict__ out,
    int nrows)
{
    __shared__ __align__(128) float tile[ROWS_PER_BLK * DIM];  // 32 KB
    __shared__ float srecip[ROWS_PER_BLK];
    __shared__ __align__(8) unsigned long long mbar;

    int t = threadIdx.x;
    int row0 = blockIdx.x * ROWS_PER_BLK;
    int row = row0 + t;
    bool full_tile = (row0 + ROWS_PER_BLK) <= nrows;
    uint32_t mb = smem_u32(&mbar);
    float4* tile4 = (float4*)tile;

    if (full_tile) {
        if (t == 0)
            asm volatile("mbarrier.init.shared.b64 [%0], 1;" :: "r"(mb) : "memory");
        __syncthreads();
        if (t == 0) {
            uint32_t dst = smem_u32(tile);
            const float* src = x + (long long)row0 * DIM;
            asm volatile("mbarrier.arrive.expect_tx.shared.b64 _, [%0], %1;"
                         :: "r"(mb), "r"(TILE_BYTES) : "memory");
            asm volatile(
                "cp.async.bulk.shared::cta.global.mbarrier::complete_tx::bytes "
                "[%0], [%1], %2, [%3];"
                :: "r"(dst), "l"(src), "r"(TILE_BYTES), "r"(mb) : "memory");
        }
    } else {
        // Tail tile: per-thread loads (generic proxy), coalesced chunk order.
        for (int k = 0; k < 8; k++) {
            int local = t + k * TPB;
            int r = row0 + (local >> 3);
            if (r < nrows)
                tile4[local] = ((const float4*)x)[(long long)r * 8 + (local & 7)];
        }
    }

    // Overlap with the in-flight TMA load: index + count read, reciprocal.
    int seg = -1;
    float recip = 0.0f;
    if (row < nrows) {
        seg = index[row];
        if ((unsigned)seg >= NUM_SEG) seg = -1;
        if (seg >= 0) {
            float c = (float)__ldg(&g_icounts[seg]);
            recip = __frcp_rn(fmaxf(c, 1.0f));
        }
    }
    srecip[t] = recip;

    if (full_tile) {
        asm volatile(
            "{\n\t.reg .pred P;\n"
            "WAIT_%=:\n\t"
            "mbarrier.try_wait.parity.shared.b64 P, [%0], 0, 0x989680;\n\t"
            "@!P bra WAIT_%=;\n\t}"
            :: "r"(mb) : "memory");
    }
    __syncthreads();   // tile (tail path) + srecip visible to all

    // Cooperative scale: chunk c = t + k*TPB -> conflict-free LDS/STS.128.
    // (Per-own-row scaling would hit a 32-way bank conflict: 128B row stride
    //  wraps the 32 banks exactly.)
    int rows_here = full_tile ? ROWS_PER_BLK
                              : (nrows - row0 > 0 ? nrows - row0 : 0);
    int chunks = rows_here * 8;
    #pragma unroll
    for (int k = 0; k < 8; k++) {
        int c = t + k * TPB;
        if (c < chunks) {
            float r = srecip[c >> 3];
            float4 v = tile4[c];
            v.x *= r; v.y *= r; v.z *= r; v.w *= r;
            tile4[c] = v;
        }
    }
    __syncthreads();
    asm volatile("fence.proxy.async.shared::cta;" ::: "memory");

    if (seg >= 0) {
        uint32_t saddr = smem_u32(&tile[t * DIM]);
        float* gdst = out + (long long)seg * DIM;
        asm volatile(
            "cp.reduce.async.bulk.global.shared::cta.bulk_group.add.f32 [%0], [%1], %2;"
            :: "l"(gdst), "r"(saddr), "r"(DIM * 4) : "memory");
    }
    // Drain bulk ops before CTA exit (smem is read asynchronously).
    asm volatile("cp.async.bulk.commit_group;" ::: "memory");
    asm volatile("cp.async.bulk.wait_group 0;" ::: "memory");
}

extern "C" void kernel_launch(void* const* d_in, const int* in_sizes, int n_in,
                              void* d_out, int out_size) {
    const float* x = (const float*)d_in[0];
    const int* index = (const int*)d_in[1];
    float* out = (float*)d_out;

    int nrows = in_sizes[1];   // 4,000,000
    int total = out_size;      // NUM_SEG * DIM

    void* counts_ptr = nullptr;
    cudaGetSymbolAddress(&counts_ptr, g_icounts);
    cudaMemsetAsync(counts_ptr, 0, (size_t)NUM_SEG * sizeof(int), 0);
    cudaMemsetAsync(out, 0, (size_t)total * sizeof(float), 0);

    int n4 = nrows >> 2;
    int cb = (n4 + TPB - 1) / TPB;
    count_kernel<<<cb, TPB>>>((const int4*)index, n4, index, nrows);

    int sb = (nrows + ROWS_PER_BLK - 1) / ROWS_PER_BLK;
    scatter_kernel<<<sb, TPB>>>(x, index, out, nrows);
}

// round 11
// speedup vs baseline: 1.1341x; 1.1341x over previous
#include <cuda_runtime.h>
#include <cstdint>

#define NUM_SEG 100000
#define DIM 32
#define TPB 256
#define ROWS_PER_BLK 512
#define TILE_BYTES (ROWS_PER_BLK * DIM * 4)   // 64 KB
#define SEGS_PER_BLK 256
#define DTILE_BYTES (SEGS_PER_BLK * DIM * 4)  // 32 KB

// Scratch: per-segment counts (allocation-free rule => __device__ global)
__device__ float g_counts[NUM_SEG];

__device__ __forceinline__ uint32_t smem_u32(const void* p) {
    uint32_t a;
    asm("{ .reg .u64 t; cvta.to.shared.u64 t, %1; cvt.u32.u64 %0, t; }" : "=r"(a) : "l"(p));
    return a;
}

__device__ __forceinline__ void mbar_wait(uint32_t mb, int parity) {
    asm volatile(
        "{\n\t.reg .pred P;\n"
        "WAIT_%=:\n\t"
        "mbarrier.try_wait.parity.shared.b64 P, [%0], %1, 0x989680;\n\t"
        "@!P bra WAIT_%=;\n\t}"
        :: "r"(mb), "r"(parity) : "memory");
}

// R9 dataflow, 512-row tiles: one 64 KB cp.async.bulk stages the tile; each
// thread owns 2 rows -> 2 cp.reduce.async.bulk (128 B f32-add) + 2 count
// atomics (issued while the TMA load is in flight).
__global__ void __launch_bounds__(TPB) scatter_kernel(
    const float* __restrict__ x,
    const int* __restrict__ index,
    float* __restrict__ out,
    int nrows)
{
    __shared__ __align__(128) float tile[ROWS_PER_BLK * DIM];  // 64 KB
    __shared__ __align__(8) unsigned long long mbar;

    int t = threadIdx.x;
    int row0 = blockIdx.x * ROWS_PER_BLK;
    bool full_tile = (row0 + ROWS_PER_BLK) <= nrows;
    uint32_t mb = smem_u32(&mbar);

    int r0 = row0 + t;
    int r1 = row0 + t + TPB;

    if (full_tile) {
        if (t == 0)
            asm volatile("mbarrier.init.shared.b64 [%0], 1;" :: "r"(mb) : "memory");
        __syncthreads();
        if (t == 0) {
            uint32_t dst = smem_u32(tile);
            const float* src = x + (long long)row0 * DIM;
            asm volatile("mbarrier.arrive.expect_tx.shared.b64 _, [%0], %1;"
                         :: "r"(mb), "r"(TILE_BYTES) : "memory");
            asm volatile(
                "cp.async.bulk.shared::cta.global.mbarrier::complete_tx::bytes "
                "[%0], [%1], %2, [%3];"
                :: "r"(dst), "l"(src), "r"(TILE_BYTES), "r"(mb) : "memory");
        }

        // Overlap with the in-flight TMA load: index reads + count atomics.
        int seg0 = index[r0];
        int seg1 = index[r1];
        if ((unsigned)seg0 >= NUM_SEG) seg0 = -1;
        if ((unsigned)seg1 >= NUM_SEG) seg1 = -1;
        if (seg0 >= 0) atomicAdd(&g_counts[seg0], 1.0f);
        if (seg1 >= 0) atomicAdd(&g_counts[seg1], 1.0f);

        mbar_wait(mb, 0);

        if (seg0 >= 0) {
            uint32_t saddr = smem_u32(&tile[t * DIM]);
            float* gdst = out + (long long)seg0 * DIM;
            asm volatile(
                "cp.reduce.async.bulk.global.shared::cta.bulk_group.add.f32 [%0], [%1], %2;"
                :: "l"(gdst), "r"(saddr), "r"(DIM * 4) : "memory");
        }
        if (seg1 >= 0) {
            uint32_t saddr = smem_u32(&tile[(t + TPB) * DIM]);
            float* gdst = out + (long long)seg1 * DIM;
            asm volatile(
                "cp.reduce.async.bulk.global.shared::cta.bulk_group.add.f32 [%0], [%1], %2;"
                :: "l"(gdst), "r"(saddr), "r"(DIM * 4) : "memory");
        }
    } else {
        // Tail tile: per-thread loads (generic proxy), chunk order.
        for (int k = 0; k < 16; k++) {
            int local = t + k * TPB;
            int r = row0 + (local >> 3);
            if (r < nrows)
                ((float4*)tile)[local] = ((const float4*)x)[(long long)r * 8 + (local & 7)];
        }
        __syncthreads();
        asm volatile("fence.proxy.async.shared::cta;" ::: "memory");

        #pragma unroll
        for (int h = 0; h < 2; h++) {
            int r = (h == 0) ? r0 : r1;
            if (r < nrows) {
                int seg = index[r];
                if ((unsigned)seg < NUM_SEG) {
                    atomicAdd(&g_counts[seg], 1.0f);
                    uint32_t saddr = smem_u32(&tile[(t + h * TPB) * DIM]);
                    float* gdst = out + (long long)seg * DIM;
                    asm volatile(
                        "cp.reduce.async.bulk.global.shared::cta.bulk_group.add.f32 [%0], [%1], %2;"
                        :: "l"(gdst), "r"(saddr), "r"(DIM * 4) : "memory");
                }
            }
        }
    }
    asm volatile("cp.async.bulk.commit_group;" ::: "memory");
    asm volatile("cp.async.bulk.wait_group 0;" ::: "memory");
}

// Divide via TMA staging: bulk-in a 32 KB out-tile (256 segments), scale by
// 1/count in smem (counts contiguous -> coalesced load), bulk-store back.
__global__ void __launch_bounds__(TPB) divide_kernel(float* __restrict__ out) {
    __shared__ __align__(128) float dtile[SEGS_PER_BLK * DIM];  // 32 KB
    __shared__ float srecip[SEGS_PER_BLK];
    __shared__ __align__(8) unsigned long long mbar;

    int t = threadIdx.x;
    int seg0 = blockIdx.x * SEGS_PER_BLK;
    bool full = (seg0 + SEGS_PER_BLK) <= NUM_SEG;
    uint32_t mb = smem_u32(&mbar);
    float4* dtile4 = (float4*)dtile;
    int nseg_here = full ? SEGS_PER_BLK : (NUM_SEG - seg0);

    if (full) {
        if (t == 0)
            asm volatile("mbarrier.init.shared.b64 [%0], 1;" :: "r"(mb) : "memory");
        __syncthreads();
        if (t == 0) {
            uint32_t dst = smem_u32(dtile);
            const float* src = out + (long long)seg0 * DIM;
            asm volatile("mbarrier.arrive.expect_tx.shared.b64 _, [%0], %1;"
                         :: "r"(mb), "r"(DTILE_BYTES) : "memory");
            asm volatile(
                "cp.async.bulk.shared::cta.global.mbarrier::complete_tx::bytes "
                "[%0], [%1], %2, [%3];"
                :: "r"(dst), "l"(src), "r"(DTILE_BYTES), "r"(mb) : "memory");
        }
    } else {
        for (int k = 0; k < 8; k++) {
            int c = t + k * TPB;
            if ((c >> 3) < nseg_here)
                dtile4[c] = ((const float4*)out)[(long long)seg0 * 8 + c];
        }
    }

    // Coalesced count load + reciprocal (overlaps the TMA load).
    float recip = 1.0f;
    if (t < nseg_here) {
        float c = g_counts[seg0 + t];
        recip = __frcp_rn(fmaxf(c, 1.0f));
    }
    srecip[t] = recip;

    if (full) mbar_wait(mb, 0);
    __syncthreads();

    int chunks = nseg_here * 8;
    #pragma unroll
    for (int k = 0; k < 8; k++) {
        int c = t + k * TPB;
        if (c < chunks) {
            float r = srecip[c >> 3];
            float4 v = dtile4[c];
            v.x *= r; v.y *= r; v.z *= r; v.w *= r;
            dtile4[c] = v;
        }
    }
    __syncthreads();
    asm volatile("fence.proxy.async.shared::cta;" ::: "memory");

    if (full) {
        if (t == 0) {
            uint32_t src = smem_u32(dtile);
            float* gdst = out + (long long)seg0 * DIM;
            asm volatile(
                "cp.async.bulk.global.shared::cta.bulk_group [%0], [%1], %2;"
                :: "l"(gdst), "r"(src), "r"(DTILE_BYTES) : "memory");
            asm volatile("cp.async.bulk.commit_group;" ::: "memory");
            asm volatile("cp.async.bulk.wait_group 0;" ::: "memory");
        }
    } else {
        for (int k = 0; k < 8; k++) {
            int c = t + k * TPB;
            if ((c >> 3) < nseg_here)
                ((float4*)out)[(long long)seg0 * 8 + c] = dtile4[c];
        }
    }
}

extern "C" void kernel_launch(void* const* d_in, const int* in_sizes, int n_in,
                              void* d_out, int out_size) {
    const float* x = (const float*)d_in[0];
    const int* index = (const int*)d_in[1];
    float* out = (float*)d_out;

    int nrows = in_sizes[1];   // 4,000,000
    int total = out_size;      // NUM_SEG * DIM

    void* counts_ptr = nullptr;
    cudaGetSymbolAddress(&counts_ptr, g_counts);
    cudaMemsetAsync(out, 0, (size_t)total * sizeof(float), 0);
    cudaMemsetAsync(counts_ptr, 0, (size_t)NUM_SEG * sizeof(float), 0);

    int sb = (nrows + ROWS_PER_BLK - 1) / ROWS_PER_BLK;
    scatter_kernel<<<sb, TPB>>>(x, index, out, nrows);

    int db = (NUM_SEG + SEGS_PER_BLK - 1) / SEGS_PER_BLK;
    divide_kernel<<<db, TPB>>>(out);
}